// round 10
// baseline (speedup 1.0000x reference)
#include <cuda_runtime.h>
#include <cstdint>

#define N_NODES 50000
#define N_EDGES 800000
#define N_TOT_EDGES (N_EDGES + N_NODES)   // self-loops appended

// ------------------------- scratch (device globals; no allocs allowed) ------
__device__ float g_hf [(size_t)N_NODES * 512];   // per-layer GEMM output h
__device__ float g_buf[(size_t)N_NODES * 512];   // layer activation ping-pong
__device__ __align__(16) float g_as [N_NODES * 4];
__device__ __align__(16) float g_ad [N_NODES * 4];
// CSR by destination (built once per launch; graph static within a call)
__device__ int   g_deg [N_NODES];
__device__ int   g_off [N_NODES + 1];
__device__ int   g_cur [N_NODES];
__device__ int   g_srcs[N_TOT_EDGES];            // src ids grouped by dst

// =============================================================================
// Tensor-core GEMM: C = A[M,K] * W[Nout,K]^T (+bias, relu)
// tf32 mma.sync m16n8k8, 2-term split (hi*hi + lo*hi + hi*lo), fp32-class acc.
// 3-stage cp.async circular buffer, ONE __syncthreads per K-chunk:
//   wait(ck) -> sync -> issue(ck+2) -> compute(ck)
// The top barrier both publishes chunk ck to all warps and guarantees readers
// of the buffer stage being overwritten (stage (ck+2)%3 == (ck-1)%3) retired.
// =============================================================================
#define BM 128
#define BN 128
#define BKC 32
#define SLD 36
#define NSTAGE 3
#define TILE_FLTS (128 * SLD)
#define GEMM_SMEM_BYTES (NSTAGE * 2 * TILE_FLTS * 4)   // 108KB

__device__ __forceinline__ void mma8(float* d, const unsigned* a, const unsigned* b) {
    asm volatile(
        "mma.sync.aligned.m16n8k8.row.col.f32.tf32.tf32.f32 "
        "{%0,%1,%2,%3}, {%4,%5,%6,%7}, {%8,%9}, {%0,%1,%2,%3};"
        : "+f"(d[0]), "+f"(d[1]), "+f"(d[2]), "+f"(d[3])
        : "r"(a[0]), "r"(a[1]), "r"(a[2]), "r"(a[3]), "r"(b[0]), "r"(b[1]));
}

__device__ __forceinline__ void split_u(float v, unsigned& hi, unsigned& lo) {
    unsigned h = __float_as_uint(v) & 0xFFFFE000u;
    hi = h;
    lo = __float_as_uint(v - __uint_as_float(h));
}

__device__ __forceinline__ void cp_async16(uint32_t saddr, const void* gptr, int src_bytes) {
    asm volatile("cp.async.cg.shared.global [%0], [%1], 16, %2;"
        :: "r"(saddr), "l"(gptr), "r"(src_bytes));
}

__global__ __launch_bounds__(256) void mma_gemm_nt(
    const float* __restrict__ A, const float* __restrict__ W,
    float* __restrict__ C, const float* __restrict__ bias,
    int M, int Nout, int K, int relu)
{
    extern __shared__ float sm[];
    const uint32_t smem_u32 = (uint32_t)__cvta_generic_to_shared(sm);

    const int tid  = threadIdx.x;
    const int lane = tid & 31;
    const int wid  = tid >> 5;
    const int g    = lane >> 2;
    const int t    = lane & 3;
    const int wm   = (wid & 1) * 64;
    const int wn   = (wid >> 1) * 32;
    const int mBase = blockIdx.y * BM;
    const int nBase = blockIdx.x * BN;

    const int lr = tid >> 3;
    const int lc = (tid & 7) * 4;

    float acc[4][4][4];
    #pragma unroll
    for (int mt = 0; mt < 4; mt++)
        #pragma unroll
        for (int nt = 0; nt < 4; nt++)
            #pragma unroll
            for (int i = 0; i < 4; i++) acc[mt][nt][i] = 0.0f;

    const int nk = K / BKC;

    auto issue_chunk = [&](int ck, int st) {
        const int k0 = ck * BKC;
        const uint32_t aOff = smem_u32 + (uint32_t)(st * 2 * TILE_FLTS) * 4;
        const uint32_t bOff = aOff + (uint32_t)TILE_FLTS * 4;
        #pragma unroll
        for (int i = 0; i < 4; i++) {
            int r = lr + i * 32;
            int arow = mBase + r;
            int ok = arow < M;
            const float* ag = A + (size_t)(ok ? arow : 0) * K + k0 + lc;
            cp_async16(aOff + (uint32_t)(r * SLD + lc) * 4, ag, ok ? 16 : 0);
            const float* bg = W + (size_t)(nBase + r) * K + k0 + lc;
            cp_async16(bOff + (uint32_t)(r * SLD + lc) * 4, bg, 16);
        }
        asm volatile("cp.async.commit_group;");
    };

    // prologue: 2 chunks in flight (nk >= 2 at all call sites: K >= 64)
    issue_chunk(0, 0);
    issue_chunk(1, 1);

    for (int ck = 0; ck < nk; ck++) {
        const int st = ck % NSTAGE;
        if (ck + 1 < nk) { asm volatile("cp.async.wait_group 1;"); }
        else             { asm volatile("cp.async.wait_group 0;"); }
        __syncthreads();
        if (ck + 2 < nk) issue_chunk(ck + 2, (ck + 2) % NSTAGE);

        const float* Ac = sm + st * 2 * TILE_FLTS;
        const float* Bc = Ac + TILE_FLTS;
        #pragma unroll
        for (int kk = 0; kk < 4; kk++) {
            const int kb = kk * 8;
            unsigned ah[4][4], al[4][4], bh[4][2], bl[4][2];
            #pragma unroll
            for (int mt = 0; mt < 4; mt++) {
                const float* p = Ac + (wm + mt * 16 + g) * SLD + kb + t;
                split_u(p[0],           ah[mt][0], al[mt][0]);
                split_u(p[8 * SLD],     ah[mt][1], al[mt][1]);
                split_u(p[4],           ah[mt][2], al[mt][2]);
                split_u(p[8 * SLD + 4], ah[mt][3], al[mt][3]);
            }
            #pragma unroll
            for (int nt = 0; nt < 4; nt++) {
                const float* p = Bc + (wn + nt * 8 + g) * SLD + kb + t;
                split_u(p[0], bh[nt][0], bl[nt][0]);
                split_u(p[4], bh[nt][1], bl[nt][1]);
            }
            #pragma unroll
            for (int mt = 0; mt < 4; mt++)
                #pragma unroll
                for (int nt = 0; nt < 4; nt++) {
                    mma8(acc[mt][nt], ah[mt], bh[nt]);
                    mma8(acc[mt][nt], al[mt], bh[nt]);
                    mma8(acc[mt][nt], ah[mt], bl[nt]);
                }
        }
    }

    #pragma unroll
    for (int mt = 0; mt < 4; mt++) {
        int row0 = mBase + wm + mt * 16 + g;
        #pragma unroll
        for (int nt = 0; nt < 4; nt++) {
            int col = nBase + wn + nt * 8 + 2 * t;
            float b0 = bias ? bias[col]     : 0.f;
            float b1 = bias ? bias[col + 1] : 0.f;
            if (row0 < M) {
                float v0 = acc[mt][nt][0] + b0;
                float v1 = acc[mt][nt][1] + b1;
                if (relu) { v0 = fmaxf(v0, 0.f); v1 = fmaxf(v1, 0.f); }
                C[(size_t)row0 * Nout + col]     = v0;
                C[(size_t)row0 * Nout + col + 1] = v1;
            }
            if (row0 + 8 < M) {
                float v2 = acc[mt][nt][2] + b0;
                float v3 = acc[mt][nt][3] + b1;
                if (relu) { v2 = fmaxf(v2, 0.f); v3 = fmaxf(v3, 0.f); }
                C[(size_t)(row0 + 8) * Nout + col]     = v2;
                C[(size_t)(row0 + 8) * Nout + col + 1] = v3;
            }
        }
    }
}

// =============================================================================
// CSR build (once per launch)
// =============================================================================
__global__ void csr_count(const int* __restrict__ ei, int* __restrict__ deg) {
    int e = blockIdx.x * blockDim.x + threadIdx.x;
    if (e >= N_TOT_EDGES) return;
    int d = (e < N_EDGES) ? ei[N_EDGES + e] : (e - N_EDGES);
    atomicAdd(&deg[d], 1);
}

__global__ __launch_bounds__(1024) void csr_scan(
    const int* __restrict__ deg, int* __restrict__ off, int* __restrict__ cur)
{
    __shared__ int part[1024];
    const int tid = threadIdx.x;
    const int chunk = (N_NODES + 1023) / 1024;
    const int b = tid * chunk;
    const int e = min(b + chunk, N_NODES);
    int s = 0;
    for (int i = b; i < e; i++) s += deg[i];
    part[tid] = s;
    __syncthreads();
    for (int o = 1; o < 1024; o <<= 1) {
        int v = (tid >= o) ? part[tid - o] : 0;
        __syncthreads();
        part[tid] += v;
        __syncthreads();
    }
    int run = tid ? part[tid - 1] : 0;
    for (int i = b; i < e; i++) {
        off[i] = run; cur[i] = run;
        run += deg[i];
    }
    if (tid == 1023) off[N_NODES] = run;
}

__global__ void csr_scatter(const int* __restrict__ ei,
    int* __restrict__ cur, int* __restrict__ srcs)
{
    int e = blockIdx.x * blockDim.x + threadIdx.x;
    if (e >= N_TOT_EDGES) return;
    int s, d;
    if (e < N_EDGES) { s = ei[e]; d = ei[N_EDGES + e]; } else { s = d = e - N_EDGES; }
    int pos = atomicAdd(&cur[d], 1);
    srcs[pos] = s;
}

// ------------------------- per-node attention logits ------------------------
__global__ void compute_alphas(const float* __restrict__ hf,
    const float* __restrict__ a_src, const float* __restrict__ a_dst,
    float* __restrict__ as_, float* __restrict__ ad_, int H)
{
    int n    = blockIdx.x;
    int head = threadIdx.y;
    int lane = threadIdx.x;
    const float* hp = hf + ((size_t)n * H + head) * 128;
    float s1 = 0.f, s2 = 0.f;
    #pragma unroll
    for (int c = lane; c < 128; c += 32) {
        float hv = hp[c];
        s1 += hv * a_src[head*128 + c];
        s2 += hv * a_dst[head*128 + c];
    }
    #pragma unroll
    for (int o = 16; o > 0; o >>= 1) {
        s1 += __shfl_down_sync(0xffffffffu, s1, o);
        s2 += __shfl_down_sync(0xffffffffu, s2, o);
    }
    if (lane == 0) { as_[n*H + head] = s1; ad_[n*H + head] = s2; }
}

// =============================================================================
// Fused GAT aggregate, H=4: ONE warp per destination node handles ALL 4 heads.
// srcs[] walk + alpha loads amortized 4x; alphas of all heads = one float4
// broadcast; 4x independent h loads per edge for deep MLP. No atomics.
// =============================================================================
__global__ __launch_bounds__(256) void gat_aggregate4(
    const int* __restrict__ off, const int* __restrict__ srcs,
    const float* __restrict__ as_, const float* __restrict__ ad_,
    const float* __restrict__ hf, const float* __restrict__ bias,
    float* __restrict__ out)
{
    const int n    = (blockIdx.x * blockDim.x + threadIdx.x) >> 5;
    const int lane = threadIdx.x & 31;
    if (n >= N_NODES) return;

    const float4 ad4 = *(const float4*)(ad_ + n * 4);
    const int beg = off[n];
    const int end = off[n + 1];
    const int co  = lane * 4;

    float4 a0 = make_float4(0.f,0.f,0.f,0.f);
    float4 a1 = a0, a2 = a0, a3 = a0;
    float4 z  = a0;

    for (int i = beg; i < end; i++) {
        const int s = srcs[i];
        const float4 av = *(const float4*)(as_ + s * 4);   // broadcast
        float e0 = av.x + ad4.x; e0 = e0 > 0.f ? e0 : 0.2f * e0;
        float e1 = av.y + ad4.y; e1 = e1 > 0.f ? e1 : 0.2f * e1;
        float e2 = av.z + ad4.z; e2 = e2 > 0.f ? e2 : 0.2f * e2;
        float e3 = av.w + ad4.w; e3 = e3 > 0.f ? e3 : 0.2f * e3;
        const float w0 = __expf(e0), w1 = __expf(e1), w2 = __expf(e2), w3 = __expf(e3);
        z.x += w0; z.y += w1; z.z += w2; z.w += w3;

        const float* hb = hf + (size_t)s * 512;
        const float4 h0 = *(const float4*)(hb +   0 + co);
        const float4 h1 = *(const float4*)(hb + 128 + co);
        const float4 h2 = *(const float4*)(hb + 256 + co);
        const float4 h3 = *(const float4*)(hb + 384 + co);
        a0.x = fmaf(w0, h0.x, a0.x); a0.y = fmaf(w0, h0.y, a0.y);
        a0.z = fmaf(w0, h0.z, a0.z); a0.w = fmaf(w0, h0.w, a0.w);
        a1.x = fmaf(w1, h1.x, a1.x); a1.y = fmaf(w1, h1.y, a1.y);
        a1.z = fmaf(w1, h1.z, a1.z); a1.w = fmaf(w1, h1.w, a1.w);
        a2.x = fmaf(w2, h2.x, a2.x); a2.y = fmaf(w2, h2.y, a2.y);
        a2.z = fmaf(w2, h2.z, a2.z); a2.w = fmaf(w2, h2.w, a2.w);
        a3.x = fmaf(w3, h3.x, a3.x); a3.y = fmaf(w3, h3.y, a3.y);
        a3.z = fmaf(w3, h3.z, a3.z); a3.w = fmaf(w3, h3.w, a3.w);
    }

    const float i0 = 1.0f / (z.x + 1e-16f);
    const float i1 = 1.0f / (z.y + 1e-16f);
    const float i2 = 1.0f / (z.z + 1e-16f);
    const float i3 = 1.0f / (z.w + 1e-16f);
    float* ob = out + (size_t)n * 512;
    #pragma unroll
    for (int h = 0; h < 4; h++) {
        const float4 ac = (h == 0) ? a0 : (h == 1) ? a1 : (h == 2) ? a2 : a3;
        const float iv = (h == 0) ? i0 : (h == 1) ? i1 : (h == 2) ? i2 : i3;
        const float4 bz = *(const float4*)(bias + h * 128 + co);
        float4 r;
        r.x = fmaxf(ac.x * iv + bz.x, 0.f);   // layers 0/1 always relu
        r.y = fmaxf(ac.y * iv + bz.y, 0.f);
        r.z = fmaxf(ac.z * iv + bz.z, 0.f);
        r.w = fmaxf(ac.w * iv + bz.w, 0.f);
        *(float4*)(ob + h * 128 + co) = r;
    }
}

// H=1 variant (layer 2): warp per node, single head, no relu
__global__ __launch_bounds__(256) void gat_aggregate1(
    const int* __restrict__ off, const int* __restrict__ srcs,
    const float* __restrict__ as_, const float* __restrict__ ad_,
    const float* __restrict__ hf, const float* __restrict__ bias,
    float* __restrict__ out)
{
    const int n    = (blockIdx.x * blockDim.x + threadIdx.x) >> 5;
    const int lane = threadIdx.x & 31;
    if (n >= N_NODES) return;

    const float adn = ad_[n];
    const int beg = off[n];
    const int end = off[n + 1];
    const int co  = lane * 4;

    float4 acc = make_float4(0.f,0.f,0.f,0.f);
    float zsum = 0.f;
    for (int i = beg; i < end; i++) {
        const int s = srcs[i];
        float e = as_[s] + adn;
        e = e > 0.f ? e : 0.2f * e;
        const float a = __expf(e);
        zsum += a;
        const float4 hx = *(const float4*)(hf + ((size_t)s << 7) + co);
        acc.x = fmaf(a, hx.x, acc.x);
        acc.y = fmaf(a, hx.y, acc.y);
        acc.z = fmaf(a, hx.z, acc.z);
        acc.w = fmaf(a, hx.w, acc.w);
    }
    const float inv = 1.0f / (zsum + 1e-16f);
    const float4 bz = *(const float4*)(bias + co);
    float4 r;
    r.x = acc.x * inv + bz.x;
    r.y = acc.y * inv + bz.y;
    r.z = acc.z * inv + bz.z;
    r.w = acc.w * inv + bz.w;
    *(float4*)(out + ((size_t)n << 7) + co) = r;
}

// ------------------------- host orchestration -------------------------------
static void launch_gemm(const float* A, const float* W, float* C,
                        const float* bias, int M, int Nout, int K, int relu)
{
    dim3 grid(Nout / BN, (M + BM - 1) / BM);
    mma_gemm_nt<<<grid, 256, GEMM_SMEM_BYTES>>>(A, W, C, bias, M, Nout, K, relu);
}

extern "C" void kernel_launch(void* const* d_in, const int* in_sizes, int n_in,
                              void* d_out, int out_size)
{
    const float* x   = (const float*)d_in[0];
    const int*   ei  = (const int*)  d_in[1];
    const float* W0  = (const float*)d_in[2];
    const float* as0 = (const float*)d_in[3];
    const float* ad0 = (const float*)d_in[4];
    const float* b0  = (const float*)d_in[5];
    const float* W1  = (const float*)d_in[6];
    const float* as1 = (const float*)d_in[7];
    const float* ad1 = (const float*)d_in[8];
    const float* b1  = (const float*)d_in[9];
    const float* W2  = (const float*)d_in[10];
    const float* as2 = (const float*)d_in[11];
    const float* ad2 = (const float*)d_in[12];
    const float* b2  = (const float*)d_in[13];
    const float* Wv  = (const float*)d_in[14];
    const float* bv  = (const float*)d_in[15];
    const float* Wt  = (const float*)d_in[16];
    const float* bt  = (const float*)d_in[17];

    cudaFuncSetAttribute(mma_gemm_nt,
                         cudaFuncAttributeMaxDynamicSharedMemorySize,
                         GEMM_SMEM_BYTES);

    float *hf, *buf, *as_, *ad_;
    int *deg, *off, *cur, *srcs;
    cudaGetSymbolAddress((void**)&hf,   g_hf);
    cudaGetSymbolAddress((void**)&buf,  g_buf);
    cudaGetSymbolAddress((void**)&as_,  g_as);
    cudaGetSymbolAddress((void**)&ad_,  g_ad);
    cudaGetSymbolAddress((void**)&deg,  g_deg);
    cudaGetSymbolAddress((void**)&off,  g_off);
    cudaGetSymbolAddress((void**)&cur,  g_cur);
    cudaGetSymbolAddress((void**)&srcs, g_srcs);

    float* out = (float*)d_out;
    float* h2  = out;                               // [N,128]
    float* xv  = out + (size_t)N_NODES * 128;       // [N,128]
    float* xt  = out + (size_t)N_NODES * 256;       // [N,128]

    // ---- CSR build ----
    cudaMemsetAsync(deg, 0, N_NODES * sizeof(int));
    csr_count  <<<(N_TOT_EDGES + 255)/256, 256>>>(ei, deg);
    csr_scan   <<<1, 1024>>>(deg, off, cur);
    csr_scatter<<<(N_TOT_EDGES + 255)/256, 256>>>(ei, cur, srcs);

    const int aggGrid = (N_NODES * 32 + 255) / 256;

    // layer 0: 512 -> 4x128, relu
    launch_gemm(x, W0, hf, nullptr, N_NODES, 512, 512, 0);
    compute_alphas<<<N_NODES, dim3(32, 4)>>>(hf, as0, ad0, as_, ad_, 4);
    gat_aggregate4<<<aggGrid, 256>>>(off, srcs, as_, ad_, hf, b0, buf);

    // layer 1: 512 -> 4x128, relu
    launch_gemm(buf, W1, hf, nullptr, N_NODES, 512, 512, 0);
    compute_alphas<<<N_NODES, dim3(32, 4)>>>(hf, as1, ad1, as_, ad_, 4);
    gat_aggregate4<<<aggGrid, 256>>>(off, srcs, as_, ad_, hf, b1, buf);

    // layer 2: 512 -> 1x128, no relu, writes h into d_out
    launch_gemm(buf, W2, hf, nullptr, N_NODES, 128, 512, 0);
    compute_alphas<<<N_NODES, dim3(32, 1)>>>(hf, as2, ad2, as_, ad_, 1);
    gat_aggregate1<<<aggGrid, 256>>>(off, srcs, as_, ad_, hf, b2, h2);

    // output heads
    launch_gemm(h2, Wv, xv, bv, N_NODES, 128, 128, 1);
    launch_gemm(h2, Wt, xt, bt, N_NODES, 128, 128, 1);
}

// round 13
// speedup vs baseline: 1.3052x; 1.3052x over previous
#include <cuda_runtime.h>
#include <cstdint>

#define N_NODES 50000
#define N_EDGES 800000
#define N_TOT_EDGES (N_EDGES + N_NODES)   // self-loops appended

// ------------------------- scratch (device globals; no allocs allowed) ------
__device__ float g_hf [(size_t)N_NODES * 512];   // per-layer GEMM output h
__device__ float g_buf[(size_t)N_NODES * 512];   // layer activation ping-pong
__device__ __align__(16) float g_as [N_NODES * 4];
__device__ __align__(16) float g_ad [N_NODES * 4];
// CSR by destination (built once per launch; graph static within a call)
__device__ int   g_deg [N_NODES];
__device__ int   g_off [N_NODES + 1];
__device__ int   g_cur [N_NODES];
__device__ int   g_srcs[N_TOT_EDGES];            // src ids grouped by dst

// ------------------------- shared GEMM helpers ------------------------------
__device__ __forceinline__ void mma8(float* d, const unsigned* a, const unsigned* b) {
    asm volatile(
        "mma.sync.aligned.m16n8k8.row.col.f32.tf32.tf32.f32 "
        "{%0,%1,%2,%3}, {%4,%5,%6,%7}, {%8,%9}, {%0,%1,%2,%3};"
        : "+f"(d[0]), "+f"(d[1]), "+f"(d[2]), "+f"(d[3])
        : "r"(a[0]), "r"(a[1]), "r"(a[2]), "r"(a[3]), "r"(b[0]), "r"(b[1]));
}

__device__ __forceinline__ void split_u(float v, unsigned& hi, unsigned& lo) {
    unsigned h = __float_as_uint(v) & 0xFFFFE000u;
    hi = h;
    lo = __float_as_uint(v - __uint_as_float(h));
}

__device__ __forceinline__ void cp_async16(uint32_t saddr, const void* gptr, int src_bytes) {
    asm volatile("cp.async.cg.shared.global [%0], [%1], 16, %2;"
        :: "r"(saddr), "l"(gptr), "r"(src_bytes));
}

#define BKC 32
#define SLD 36

// =============================================================================
// Narrow GEMM (R9-proven, unchanged): 128x128 CTA, 8 warps of 64x32, 2-stage.
// Used for Nout == 128 launches (layer 2 + output heads).
// =============================================================================
#define BM 128
#define BN 128
#define GEMM_SMEM_BYTES (4 * 128 * SLD * 4)   // 72KB

__global__ __launch_bounds__(256) void mma_gemm_nt(
    const float* __restrict__ A, const float* __restrict__ W,
    float* __restrict__ C, const float* __restrict__ bias,
    int M, int Nout, int K, int relu)
{
    extern __shared__ float sm[];
    float* Asm[2] = { sm,               sm + 128 * SLD };
    float* Bsm[2] = { sm + 2*128*SLD,   sm + 3*128*SLD };
    const uint32_t smem_u32 = (uint32_t)__cvta_generic_to_shared(sm);

    const int tid  = threadIdx.x;
    const int lane = tid & 31;
    const int wid  = tid >> 5;
    const int g    = lane >> 2;
    const int t    = lane & 3;
    const int wm   = (wid & 1) * 64;
    const int wn   = (wid >> 1) * 32;
    const int mBase = blockIdx.y * BM;
    const int nBase = blockIdx.x * BN;

    const int lr = tid >> 3;
    const int lc = (tid & 7) * 4;

    float acc[4][4][4];
    #pragma unroll
    for (int mt = 0; mt < 4; mt++)
        #pragma unroll
        for (int nt = 0; nt < 4; nt++)
            #pragma unroll
            for (int i = 0; i < 4; i++) acc[mt][nt][i] = 0.0f;

    const int nk = K / BKC;

    auto issue_chunk = [&](int ck, int b) {
        const int k0 = ck * BKC;
        const uint32_t aOff = smem_u32 + (uint32_t)(b * 128 * SLD) * 4;
        const uint32_t bOff = smem_u32 + (uint32_t)((2 + b) * 128 * SLD) * 4;
        #pragma unroll
        for (int i = 0; i < 4; i++) {
            int r = lr + i * 32;
            int arow = mBase + r;
            int ok = arow < M;
            const float* ag = A + (size_t)(ok ? arow : 0) * K + k0 + lc;
            cp_async16(aOff + (uint32_t)(r * SLD + lc) * 4, ag, ok ? 16 : 0);
            const float* bg = W + (size_t)(nBase + r) * K + k0 + lc;
            cp_async16(bOff + (uint32_t)(r * SLD + lc) * 4, bg, 16);
        }
        asm volatile("cp.async.commit_group;");
    };

    issue_chunk(0, 0);

    for (int ck = 0; ck < nk; ck++) {
        const int cur = ck & 1;
        if (ck + 1 < nk) {
            issue_chunk(ck + 1, cur ^ 1);
            asm volatile("cp.async.wait_group 1;");
        } else {
            asm volatile("cp.async.wait_group 0;");
        }
        __syncthreads();

        const float* Ac = Asm[cur];
        const float* Bc = Bsm[cur];
        #pragma unroll
        for (int kk = 0; kk < 4; kk++) {
            const int kb = kk * 8;
            unsigned ah[4][4], al[4][4], bh[4][2], bl[4][2];
            #pragma unroll
            for (int mt = 0; mt < 4; mt++) {
                const float* p = Ac + (wm + mt * 16 + g) * SLD + kb + t;
                split_u(p[0],           ah[mt][0], al[mt][0]);
                split_u(p[8 * SLD],     ah[mt][1], al[mt][1]);
                split_u(p[4],           ah[mt][2], al[mt][2]);
                split_u(p[8 * SLD + 4], ah[mt][3], al[mt][3]);
            }
            #pragma unroll
            for (int nt = 0; nt < 4; nt++) {
                const float* p = Bc + (wn + nt * 8 + g) * SLD + kb + t;
                split_u(p[0], bh[nt][0], bl[nt][0]);
                split_u(p[4], bh[nt][1], bl[nt][1]);
            }
            #pragma unroll
            for (int mt = 0; mt < 4; mt++)
                #pragma unroll
                for (int nt = 0; nt < 4; nt++) {
                    mma8(acc[mt][nt], ah[mt], bh[nt]);
                    mma8(acc[mt][nt], al[mt], bh[nt]);
                    mma8(acc[mt][nt], ah[mt], bl[nt]);
                }
        }
        __syncthreads();
    }

    #pragma unroll
    for (int mt = 0; mt < 4; mt++) {
        int row0 = mBase + wm + mt * 16 + g;
        #pragma unroll
        for (int nt = 0; nt < 4; nt++) {
            int col = nBase + wn + nt * 8 + 2 * t;
            float b0 = bias ? bias[col]     : 0.f;
            float b1 = bias ? bias[col + 1] : 0.f;
            if (row0 < M) {
                float v0 = acc[mt][nt][0] + b0;
                float v1 = acc[mt][nt][1] + b1;
                if (relu) { v0 = fmaxf(v0, 0.f); v1 = fmaxf(v1, 0.f); }
                C[(size_t)row0 * Nout + col]     = v0;
                C[(size_t)row0 * Nout + col + 1] = v1;
            }
            if (row0 + 8 < M) {
                float v2 = acc[mt][nt][2] + b0;
                float v3 = acc[mt][nt][3] + b1;
                if (relu) { v2 = fmaxf(v2, 0.f); v3 = fmaxf(v3, 0.f); }
                C[(size_t)(row0 + 8) * Nout + col]     = v2;
                C[(size_t)(row0 + 8) * Nout + col + 1] = v3;
            }
        }
    }
}

// =============================================================================
// Wide GEMM: 128x256 CTA, 8 warps of 64x64, 2-stage cp.async (R9 schedule).
// Raises mma:issue ratio (96 mma vs ~210 issues per kk per warp; 2 warps/SMSP
// -> tensor pipe becomes the binding resource instead of issue bandwidth).
// Requires Nout % 256 == 0. 1 CTA/SM (regs), smem 108KB.
// =============================================================================
#define WBM 128
#define WBN 256
#define WSTG_FLTS ((WBM + WBN) * SLD)                 // floats per stage
#define WGEMM_SMEM_BYTES (2 * WSTG_FLTS * 4)          // 110,592 B

__global__ __launch_bounds__(256, 1) void mma_gemm_nt_wide(
    const float* __restrict__ A, const float* __restrict__ W,
    float* __restrict__ C, int M, int Nout, int K)
{
    extern __shared__ float sm[];
    const uint32_t smem_u32 = (uint32_t)__cvta_generic_to_shared(sm);

    const int tid  = threadIdx.x;
    const int lane = tid & 31;
    const int wid  = tid >> 5;
    const int g    = lane >> 2;
    const int t    = lane & 3;
    const int wm   = (wid & 1) * 64;       // 2 warps along M
    const int wn   = (wid >> 1) * 64;      // 4 warps along N
    const int mBase = blockIdx.y * WBM;
    const int nBase = blockIdx.x * WBN;

    const int lr = tid >> 3;               // 0..31
    const int lc = (tid & 7) * 4;          // 0..28

    float acc[4][8][4];
    #pragma unroll
    for (int mt = 0; mt < 4; mt++)
        #pragma unroll
        for (int nt = 0; nt < 8; nt++)
            #pragma unroll
            for (int i = 0; i < 4; i++) acc[mt][nt][i] = 0.0f;

    const int nk = K / BKC;

    auto issue_chunk = [&](int ck, int b) {
        const int k0 = ck * BKC;
        const uint32_t aOff = smem_u32 + (uint32_t)(b * WSTG_FLTS) * 4;
        const uint32_t bOff = aOff + (uint32_t)(WBM * SLD) * 4;
        #pragma unroll
        for (int i = 0; i < 4; i++) {       // A: 128 rows
            int r = lr + i * 32;
            int arow = mBase + r;
            int ok = arow < M;
            const float* ag = A + (size_t)(ok ? arow : 0) * K + k0 + lc;
            cp_async16(aOff + (uint32_t)(r * SLD + lc) * 4, ag, ok ? 16 : 0);
        }
        #pragma unroll
        for (int i = 0; i < 8; i++) {       // B: 256 rows (always in-bounds)
            int r = lr + i * 32;
            const float* bg = W + (size_t)(nBase + r) * K + k0 + lc;
            cp_async16(bOff + (uint32_t)(r * SLD + lc) * 4, bg, 16);
        }
        asm volatile("cp.async.commit_group;");
    };

    issue_chunk(0, 0);

    for (int ck = 0; ck < nk; ck++) {
        const int cur = ck & 1;
        if (ck + 1 < nk) {
            issue_chunk(ck + 1, cur ^ 1);
            asm volatile("cp.async.wait_group 1;");
        } else {
            asm volatile("cp.async.wait_group 0;");
        }
        __syncthreads();

        const float* Ac = sm + cur * WSTG_FLTS;
        const float* Bc = Ac + WBM * SLD;
        #pragma unroll
        for (int kk = 0; kk < 4; kk++) {
            const int kb = kk * 8;
            unsigned ah[4][4], al[4][4], bh[8][2], bl[8][2];
            #pragma unroll
            for (int mt = 0; mt < 4; mt++) {
                const float* p = Ac + (wm + mt * 16 + g) * SLD + kb + t;
                split_u(p[0],           ah[mt][0], al[mt][0]);
                split_u(p[8 * SLD],     ah[mt][1], al[mt][1]);
                split_u(p[4],           ah[mt][2], al[mt][2]);
                split_u(p[8 * SLD + 4], ah[mt][3], al[mt][3]);
            }
            #pragma unroll
            for (int nt = 0; nt < 8; nt++) {
                const float* p = Bc + (wn + nt * 8 + g) * SLD + kb + t;
                split_u(p[0], bh[nt][0], bl[nt][0]);
                split_u(p[4], bh[nt][1], bl[nt][1]);
            }
            #pragma unroll
            for (int mt = 0; mt < 4; mt++)
                #pragma unroll
                for (int nt = 0; nt < 8; nt++) {
                    mma8(acc[mt][nt], ah[mt], bh[nt]);
                    mma8(acc[mt][nt], al[mt], bh[nt]);
                    mma8(acc[mt][nt], ah[mt], bl[nt]);
                }
        }
        __syncthreads();
    }

    // epilogue (no bias/relu at wide call sites)
    #pragma unroll
    for (int mt = 0; mt < 4; mt++) {
        int row0 = mBase + wm + mt * 16 + g;
        #pragma unroll
        for (int nt = 0; nt < 8; nt++) {
            int col = nBase + wn + nt * 8 + 2 * t;
            if (row0 < M) {
                C[(size_t)row0 * Nout + col]     = acc[mt][nt][0];
                C[(size_t)row0 * Nout + col + 1] = acc[mt][nt][1];
            }
            if (row0 + 8 < M) {
                C[(size_t)(row0 + 8) * Nout + col]     = acc[mt][nt][2];
                C[(size_t)(row0 + 8) * Nout + col + 1] = acc[mt][nt][3];
            }
        }
    }
}

// =============================================================================
// CSR build (once per launch)
// =============================================================================
__global__ void csr_count(const int* __restrict__ ei, int* __restrict__ deg) {
    int e = blockIdx.x * blockDim.x + threadIdx.x;
    if (e >= N_TOT_EDGES) return;
    int d = (e < N_EDGES) ? ei[N_EDGES + e] : (e - N_EDGES);
    atomicAdd(&deg[d], 1);
}

__global__ __launch_bounds__(1024) void csr_scan(
    const int* __restrict__ deg, int* __restrict__ off, int* __restrict__ cur)
{
    __shared__ int part[1024];
    const int tid = threadIdx.x;
    const int chunk = (N_NODES + 1023) / 1024;
    const int b = tid * chunk;
    const int e = min(b + chunk, N_NODES);
    int s = 0;
    for (int i = b; i < e; i++) s += deg[i];
    part[tid] = s;
    __syncthreads();
    for (int o = 1; o < 1024; o <<= 1) {
        int v = (tid >= o) ? part[tid - o] : 0;
        __syncthreads();
        part[tid] += v;
        __syncthreads();
    }
    int run = tid ? part[tid - 1] : 0;
    for (int i = b; i < e; i++) {
        off[i] = run; cur[i] = run;
        run += deg[i];
    }
    if (tid == 1023) off[N_NODES] = run;
}

__global__ void csr_scatter(const int* __restrict__ ei,
    int* __restrict__ cur, int* __restrict__ srcs)
{
    int e = blockIdx.x * blockDim.x + threadIdx.x;
    if (e >= N_TOT_EDGES) return;
    int s, d;
    if (e < N_EDGES) { s = ei[e]; d = ei[N_EDGES + e]; } else { s = d = e - N_EDGES; }
    int pos = atomicAdd(&cur[d], 1);
    srcs[pos] = s;
}

// ------------------------- per-node attention logits ------------------------
__global__ void compute_alphas(const float* __restrict__ hf,
    const float* __restrict__ a_src, const float* __restrict__ a_dst,
    float* __restrict__ as_, float* __restrict__ ad_, int H)
{
    int n    = blockIdx.x;
    int head = threadIdx.y;
    int lane = threadIdx.x;
    const float* hp = hf + ((size_t)n * H + head) * 128;
    float s1 = 0.f, s2 = 0.f;
    #pragma unroll
    for (int c = lane; c < 128; c += 32) {
        float hv = hp[c];
        s1 += hv * a_src[head*128 + c];
        s2 += hv * a_dst[head*128 + c];
    }
    #pragma unroll
    for (int o = 16; o > 0; o >>= 1) {
        s1 += __shfl_down_sync(0xffffffffu, s1, o);
        s2 += __shfl_down_sync(0xffffffffu, s2, o);
    }
    if (lane == 0) { as_[n*H + head] = s1; ad_[n*H + head] = s2; }
}

// =============================================================================
// Fused GAT aggregate (R9-proven): one warp per (dst node, head).
// Max-free softmax (ratio-identical; logits O(1)), register accumulation,
// single store with 1/(z+eps), bias, relu. No atomics, no memset.
// =============================================================================
__global__ __launch_bounds__(256) void gat_aggregate(
    const int* __restrict__ off, const int* __restrict__ srcs,
    const float* __restrict__ as_, const float* __restrict__ ad_,
    const float* __restrict__ hf, const float* __restrict__ bias,
    float* __restrict__ out, int H, int relu)
{
    const int gw   = (blockIdx.x * blockDim.x + threadIdx.x) >> 5;
    const int lane = threadIdx.x & 31;
    if (gw >= N_NODES * H) return;
    const int n = gw / H;
    const int h = gw - n * H;

    const float adn = ad_[n*H + h];
    const int beg = off[n];
    const int end = off[n + 1];

    float4 acc = make_float4(0.f, 0.f, 0.f, 0.f);
    float zsum = 0.f;
    for (int i = beg; i < end; i++) {
        const int s = srcs[i];                       // uniform across warp
        float e = as_[s*H + h] + adn;                // broadcast load
        e = e > 0.f ? e : 0.2f * e;
        const float a = __expf(e);
        zsum += a;
        const float4 hx = *(const float4*)(hf + (((size_t)s*H + h) << 7) + lane*4);
        acc.x = fmaf(a, hx.x, acc.x);
        acc.y = fmaf(a, hx.y, acc.y);
        acc.z = fmaf(a, hx.z, acc.z);
        acc.w = fmaf(a, hx.w, acc.w);
    }
    const float inv = 1.0f / (zsum + 1e-16f);
    const int hc = h * 128 + lane * 4;
    float4 r;
    r.x = acc.x * inv + bias[hc + 0];
    r.y = acc.y * inv + bias[hc + 1];
    r.z = acc.z * inv + bias[hc + 2];
    r.w = acc.w * inv + bias[hc + 3];
    if (relu) {
        r.x = fmaxf(r.x, 0.f); r.y = fmaxf(r.y, 0.f);
        r.z = fmaxf(r.z, 0.f); r.w = fmaxf(r.w, 0.f);
    }
    *(float4*)(out + ((size_t)n * H + h) * 128 + lane * 4) = r;
}

// ------------------------- host orchestration -------------------------------
static void launch_gemm(const float* A, const float* W, float* C,
                        const float* bias, int M, int Nout, int K, int relu)
{
    if (Nout % WBN == 0 && bias == nullptr && relu == 0) {
        dim3 grid(Nout / WBN, (M + WBM - 1) / WBM);
        mma_gemm_nt_wide<<<grid, 256, WGEMM_SMEM_BYTES>>>(A, W, C, M, Nout, K);
    } else {
        dim3 grid(Nout / BN, (M + BM - 1) / BM);
        mma_gemm_nt<<<grid, 256, GEMM_SMEM_BYTES>>>(A, W, C, bias, M, Nout, K, relu);
    }
}

extern "C" void kernel_launch(void* const* d_in, const int* in_sizes, int n_in,
                              void* d_out, int out_size)
{
    const float* x   = (const float*)d_in[0];
    const int*   ei  = (const int*)  d_in[1];
    const float* W0  = (const float*)d_in[2];
    const float* as0 = (const float*)d_in[3];
    const float* ad0 = (const float*)d_in[4];
    const float* b0  = (const float*)d_in[5];
    const float* W1  = (const float*)d_in[6];
    const float* as1 = (const float*)d_in[7];
    const float* ad1 = (const float*)d_in[8];
    const float* b1  = (const float*)d_in[9];
    const float* W2  = (const float*)d_in[10];
    const float* as2 = (const float*)d_in[11];
    const float* ad2 = (const float*)d_in[12];
    const float* b2  = (const float*)d_in[13];
    const float* Wv  = (const float*)d_in[14];
    const float* bv  = (const float*)d_in[15];
    const float* Wt  = (const float*)d_in[16];
    const float* bt  = (const float*)d_in[17];

    cudaFuncSetAttribute(mma_gemm_nt,
                         cudaFuncAttributeMaxDynamicSharedMemorySize,
                         GEMM_SMEM_BYTES);
    cudaFuncSetAttribute(mma_gemm_nt_wide,
                         cudaFuncAttributeMaxDynamicSharedMemorySize,
                         WGEMM_SMEM_BYTES);

    float *hf, *buf, *as_, *ad_;
    int *deg, *off, *cur, *srcs;
    cudaGetSymbolAddress((void**)&hf,   g_hf);
    cudaGetSymbolAddress((void**)&buf,  g_buf);
    cudaGetSymbolAddress((void**)&as_,  g_as);
    cudaGetSymbolAddress((void**)&ad_,  g_ad);
    cudaGetSymbolAddress((void**)&deg,  g_deg);
    cudaGetSymbolAddress((void**)&off,  g_off);
    cudaGetSymbolAddress((void**)&cur,  g_cur);
    cudaGetSymbolAddress((void**)&srcs, g_srcs);

    float* out = (float*)d_out;
    float* h2  = out;                               // [N,128]
    float* xv  = out + (size_t)N_NODES * 128;       // [N,128]
    float* xt  = out + (size_t)N_NODES * 256;       // [N,128]

    // ---- CSR build ----
    cudaMemsetAsync(deg, 0, N_NODES * sizeof(int));
    csr_count  <<<(N_TOT_EDGES + 255)/256, 256>>>(ei, deg);
    csr_scan   <<<1, 1024>>>(deg, off, cur);
    csr_scatter<<<(N_TOT_EDGES + 255)/256, 256>>>(ei, cur, srcs);

    // layer 0: 512 -> 4x128, relu
    launch_gemm(x, W0, hf, nullptr, N_NODES, 512, 512, 0);
    compute_alphas<<<N_NODES, dim3(32, 4)>>>(hf, as0, ad0, as_, ad_, 4);
    gat_aggregate<<<(N_NODES * 4 * 32 + 255)/256, 256>>>(off, srcs, as_, ad_, hf, b0, buf, 4, 1);

    // layer 1: 512 -> 4x128, relu
    launch_gemm(buf, W1, hf, nullptr, N_NODES, 512, 512, 0);
    compute_alphas<<<N_NODES, dim3(32, 4)>>>(hf, as1, ad1, as_, ad_, 4);
    gat_aggregate<<<(N_NODES * 4 * 32 + 255)/256, 256>>>(off, srcs, as_, ad_, hf, b1, buf, 4, 1);

    // layer 2: 512 -> 1x128, no relu, writes h into d_out
    launch_gemm(buf, W2, hf, nullptr, N_NODES, 128, 512, 0);
    compute_alphas<<<N_NODES, dim3(32, 1)>>>(hf, as2, ad2, as_, ad_, 1);
    gat_aggregate<<<(N_NODES * 1 * 32 + 255)/256, 256>>>(off, srcs, as_, ad_, hf, b2, h2, 1, 0);

    // output heads
    launch_gemm(h2, Wv, xv, bv, N_NODES, 128, 128, 1);
    launch_gemm(h2, Wt, xt, bt, N_NODES, 128, 128, 1);
}